// round 1
// baseline (speedup 1.0000x reference)
#include <cuda_runtime.h>

#define BB 128
#define NN 32
#define DD 256
#define HH 1024

// 16 MB scratch for g[b,j,h] = sum_i relu( (x_i . x_j pairwise) @ W1 + b1 )
__device__ float g_buf[(size_t)BB * NN * HH];

// ---------------------------------------------------------------------------
// Kernel 1: g[b,j,h] = sum_i relu( sum_e X[b,i,e]*X[b,j,e]*W1[e,h] + b1[h] )
// Block tile: 1 batch, 4 j's x 32 i's (128 rows) x 128 h cols, K = 256.
// Thread tile: 8 i-rows x 8 h-cols (64 fp32 accumulators).
// ---------------------------------------------------------------------------
#define XS 260   // padded row stride for X smem (32 rows x 256 + pad)
#define WS 132   // padded row stride for W1 smem chunk (64 x 128 + pad)
#define K1_SMEM ((32 * XS + 64 * WS) * 4)

__global__ __launch_bounds__(256) void k1(const float* __restrict__ X,
                                          const float* __restrict__ W1,
                                          const float* __restrict__ b1)
{
    extern __shared__ float sm[];
    float* Xs = sm;              // [32][XS]
    float* Ws = sm + 32 * XS;    // [64][WS]; reused as red[4][4][128] in epilogue

    const int b  = blockIdx.z;
    const int j0 = blockIdx.y * 4;
    const int h0 = blockIdx.x * 128;
    const int tid = threadIdx.x;

    // Load full X[b] (32 x 256) into smem
    const float4* Xg = reinterpret_cast<const float4*>(X + (size_t)b * NN * DD);
    for (int t = tid; t < NN * (DD / 4); t += 256) {
        int r = t >> 6, c4 = t & 63;
        *reinterpret_cast<float4*>(Xs + r * XS + c4 * 4) = Xg[r * 64 + c4];
    }

    const int gc   = tid >> 4;   // 0..15 : col group (8 h-cols)
    const int gr   = tid & 15;   // 0..15 : row group
    const int jl   = gr >> 2;    // 0..3  : local j
    const int isub = gr & 3;     // 0..3  : i subgroup (8 i's each)
    const float* xj  = Xs + (j0 + jl) * XS;
    const float* xi0 = Xs + (isub * 8) * XS;

    float acc[8][8];
#pragma unroll
    for (int r = 0; r < 8; r++)
#pragma unroll
        for (int c = 0; c < 8; c++) acc[r][c] = 0.f;

    for (int kc = 0; kc < DD; kc += 64) {
        __syncthreads();   // X ready (iter 0) / previous Ws consumers done
        // Stage W1[kc..kc+63][h0..h0+127]
        for (int t = tid; t < 64 * 32; t += 256) {
            int e = t >> 5, c4 = t & 31;
            *reinterpret_cast<float4*>(Ws + e * WS + c4 * 4) =
                *reinterpret_cast<const float4*>(W1 + (size_t)(kc + e) * HH + h0 + c4 * 4);
        }
        __syncthreads();

#pragma unroll 4
        for (int e4 = 0; e4 < 16; e4++) {
            float4 xj4 = *reinterpret_cast<const float4*>(xj + kc + e4 * 4);
            float4 xi4[8];
#pragma unroll
            for (int r = 0; r < 8; r++)
                xi4[r] = *reinterpret_cast<const float4*>(xi0 + r * XS + kc + e4 * 4);
#pragma unroll
            for (int ee = 0; ee < 4; ee++) {
                const float* wrow = Ws + (e4 * 4 + ee) * WS + gc * 8;
                float4 wA = *reinterpret_cast<const float4*>(wrow);
                float4 wB = *reinterpret_cast<const float4*>(wrow + 4);
                float xjv = (&xj4.x)[ee];
#pragma unroll
                for (int r = 0; r < 8; r++) {
                    float pv = (&xi4[r].x)[ee] * xjv;
                    acc[r][0] += pv * wA.x; acc[r][1] += pv * wA.y;
                    acc[r][2] += pv * wA.z; acc[r][3] += pv * wA.w;
                    acc[r][4] += pv * wB.x; acc[r][5] += pv * wB.y;
                    acc[r][6] += pv * wB.z; acc[r][7] += pv * wB.w;
                }
            }
        }
    }

    // Epilogue: bias + relu + partial sum over this thread's 8 i's
    float4 b1A = *reinterpret_cast<const float4*>(b1 + h0 + gc * 8);
    float4 b1B = *reinterpret_cast<const float4*>(b1 + h0 + gc * 8 + 4);
    float bias[8] = {b1A.x, b1A.y, b1A.z, b1A.w, b1B.x, b1B.y, b1B.z, b1B.w};
    float cs[8];
#pragma unroll
    for (int c = 0; c < 8; c++) cs[c] = 0.f;
#pragma unroll
    for (int r = 0; r < 8; r++)
#pragma unroll
        for (int c = 0; c < 8; c++) cs[c] += fmaxf(acc[r][c] + bias[c], 0.f);

    __syncthreads();               // done reading Ws; reuse as reduction buffer
    float* red = Ws;               // [isub 4][jl 4][col 128]
#pragma unroll
    for (int c = 0; c < 8; c++)
        red[(isub * 4 + jl) * 128 + gc * 8 + c] = cs[c];
    __syncthreads();

    // Reduce over the 4 i-subgroups; write g[b, j0+jl, h0+col]
    for (int t = tid; t < 4 * 128; t += 256) {
        int jjl = t >> 7, col = t & 127;
        float s = red[(0 * 4 + jjl) * 128 + col] + red[(1 * 4 + jjl) * 128 + col]
                + red[(2 * 4 + jjl) * 128 + col] + red[(3 * 4 + jjl) * 128 + col];
        g_buf[(size_t)((b * NN + j0 + jjl) * HH) + h0 + col] = s;
    }
}

// ---------------------------------------------------------------------------
// Kernel 2: out[row,d] = sum_h g[row,h] * W2[h,d] + 32*b2[d],  row = b*32 + j
// Block: 16 rows x 256 cols; thread tile 4x4; K chunks of 32.
// ---------------------------------------------------------------------------
__global__ __launch_bounds__(256) void k2(const float* __restrict__ W2,
                                          const float* __restrict__ b2,
                                          float* __restrict__ out)
{
    __shared__ __align__(16) float Gs[16][36];
    __shared__ __align__(16) float Ws2[32][260];

    const int row0 = blockIdx.x * 16;
    const int tid  = threadIdx.x;
    const int gc = tid & 63;    // cols gc*4 .. +3
    const int gr = tid >> 6;    // rows gr*4 .. +3

    float acc[4][4];
#pragma unroll
    for (int r = 0; r < 4; r++)
#pragma unroll
        for (int c = 0; c < 4; c++) acc[r][c] = 0.f;

    for (int kc = 0; kc < HH; kc += 32) {
        __syncthreads();
        for (int t = tid; t < 16 * 8; t += 256) {       // 16 rows x 32 h (float4)
            int r = t >> 3, c4 = t & 7;
            *reinterpret_cast<float4*>(&Gs[r][c4 * 4]) =
                *reinterpret_cast<const float4*>(g_buf + (size_t)(row0 + r) * HH + kc + c4 * 4);
        }
        for (int t = tid; t < 32 * 64; t += 256) {      // 32 h x 256 d (float4)
            int e = t >> 6, c4 = t & 63;
            *reinterpret_cast<float4*>(&Ws2[e][c4 * 4]) =
                *reinterpret_cast<const float4*>(W2 + (size_t)(kc + e) * DD + c4 * 4);
        }
        __syncthreads();

#pragma unroll
        for (int e4 = 0; e4 < 8; e4++) {
            float4 gv[4];
#pragma unroll
            for (int r = 0; r < 4; r++)
                gv[r] = *reinterpret_cast<const float4*>(&Gs[gr * 4 + r][e4 * 4]);
#pragma unroll
            for (int ee = 0; ee < 4; ee++) {
                float4 wv = *reinterpret_cast<const float4*>(&Ws2[e4 * 4 + ee][gc * 4]);
#pragma unroll
                for (int r = 0; r < 4; r++) {
                    float gvv = (&gv[r].x)[ee];
                    acc[r][0] += gvv * wv.x; acc[r][1] += gvv * wv.y;
                    acc[r][2] += gvv * wv.z; acc[r][3] += gvv * wv.w;
                }
            }
        }
    }

    float4 bv = *reinterpret_cast<const float4*>(b2 + gc * 4);
#pragma unroll
    for (int r = 0; r < 4; r++) {
        float4 o;
        o.x = acc[r][0] + 32.f * bv.x;
        o.y = acc[r][1] + 32.f * bv.y;
        o.z = acc[r][2] + 32.f * bv.z;
        o.w = acc[r][3] + 32.f * bv.w;
        *reinterpret_cast<float4*>(out + (size_t)(row0 + gr * 4 + r) * DD + gc * 4) = o;
    }
}

extern "C" void kernel_launch(void* const* d_in, const int* in_sizes, int n_in,
                              void* d_out, int out_size)
{
    const float* X  = (const float*)d_in[0];   // [B,N,D]
    const float* W1 = (const float*)d_in[1];   // [D,H]
    const float* b1 = (const float*)d_in[2];   // [H]
    const float* W2 = (const float*)d_in[3];   // [H,D]
    const float* b2 = (const float*)d_in[4];   // [D]
    float* out = (float*)d_out;                // [B,N,D]

    cudaFuncSetAttribute(k1, cudaFuncAttributeMaxDynamicSharedMemorySize, K1_SMEM);

    dim3 grid1(HH / 128, NN / 4, BB);          // (8, 8, 128)
    k1<<<grid1, 256, K1_SMEM>>>(X, W1, b1);

    k2<<<(BB * NN) / 16, 256>>>(W2, b2, out);  // 256 blocks
}

// round 11
// speedup vs baseline: 4.9139x; 4.9139x over previous
#include <cuda_runtime.h>
#include <cstdint>

#define BB 128
#define NN 32
#define DD 256
#define HH 1024

__device__ float g_buf[(size_t)BB * NN * HH];   // 16 MB: g[b,j,h]

// ======================= k1: HMMA tf32 GEMM1 + relu + i-reduce =============
// Grid (8 hblk, 128 b), 512 threads (16 warps, 4m x 4n).
// SMEM: Xs = X[b] (32 x 256 f32, padded), Ws = W1[0:256][h0:h0+128] as tf32.
// Each warp: 32 rows (= one j per warpm per rowblk, i = 0..31) x 32 h cols.
#define XS_PAD 260
#define WS_PAD 136
#define WS_OFF (32 * XS_PAD * 4)                 // 33280
#define K1_SMEM (WS_OFF + 256 * WS_PAD * 4)      // 33280 + 139264 = 172544

__device__ __forceinline__ uint32_t f2tf32(float f) {
    uint32_t u;
    asm("cvt.rna.tf32.f32 %0, %1;" : "=r"(u) : "f"(f));
    return u;
}
__device__ __forceinline__ void mma_tf32(float* c, const uint32_t* a, uint32_t b0, uint32_t b1) {
    asm volatile(
        "mma.sync.aligned.m16n8k8.row.col.f32.tf32.tf32.f32 "
        "{%0,%1,%2,%3}, {%4,%5,%6,%7}, {%8,%9}, {%0,%1,%2,%3};"
        : "+f"(c[0]), "+f"(c[1]), "+f"(c[2]), "+f"(c[3])
        : "r"(a[0]), "r"(a[1]), "r"(a[2]), "r"(a[3]), "r"(b0), "r"(b1));
}

__global__ __launch_bounds__(512) void k1(const float* __restrict__ X,
                                          const float* __restrict__ W1,
                                          const float* __restrict__ b1)
{
    extern __shared__ char smem[];
    float* Xs = (float*)smem;
    uint32_t* Ws = (uint32_t*)(smem + WS_OFF);
    const int tid = threadIdx.x, lane = tid & 31, wid = tid >> 5;
    const int warpm = wid & 3, warpn = wid >> 2;     // 4 x 4 warp grid
    const int q = lane >> 2, kq = lane & 3;
    const int b = blockIdx.y, h0 = blockIdx.x * 128;

    // Stage Xs: X[b] 32 x 256 (float4, padded rows)
    const float4* Xg = reinterpret_cast<const float4*>(X + (size_t)b * NN * DD);
    for (int t = tid; t < 32 * 64; t += 512) {
        int r = t >> 6, c = t & 63;
        *reinterpret_cast<float4*>(Xs + r * XS_PAD + c * 4) = Xg[t];
    }
    // Stage Ws: W1[e][h0..h0+127] -> tf32 bits, [256][WS_PAD]
    for (int t = tid; t < 256 * 32; t += 512) {
        int e = t >> 5, c4 = t & 31;
        float4 v = *reinterpret_cast<const float4*>(W1 + (size_t)e * HH + h0 + c4 * 4);
        uint4 u;
        u.x = f2tf32(v.x); u.y = f2tf32(v.y); u.z = f2tf32(v.z); u.w = f2tf32(v.w);
        *reinterpret_cast<uint4*>(Ws + e * WS_PAD + c4 * 4) = u;
    }
    __syncthreads();

    // Per-thread bias values for its 8 h columns (2 per n-tile)
    float2 b1v[4];
#pragma unroll
    for (int nt = 0; nt < 4; nt++)
        b1v[nt] = *reinterpret_cast<const float2*>(b1 + h0 + warpn * 32 + nt * 8 + 2 * kq);

    for (int rowblk = 0; rowblk < 8; rowblk++) {
        const int j = rowblk * 4 + warpm;
        const float* xj = Xs + j * XS_PAD;

        float acc[2][4][4];
#pragma unroll
        for (int mt = 0; mt < 2; mt++)
#pragma unroll
            for (int nt = 0; nt < 4; nt++)
#pragma unroll
                for (int c = 0; c < 4; c++) acc[mt][nt][c] = 0.f;

#pragma unroll 4
        for (int ks = 0; ks < 32; ks++) {
            const int k0 = ks * 8 + kq;
            const float xj0 = xj[k0], xj1 = xj[k0 + 4];

            // A fragments: A[i, k] = xi[k] * xj[k];  i = mt*16 + q (+8)
            uint32_t a[2][4];
#pragma unroll
            for (int mt = 0; mt < 2; mt++) {
                const float* xr0 = Xs + (mt * 16 + q) * XS_PAD;
                const float* xr1 = xr0 + 8 * XS_PAD;
                a[mt][0] = f2tf32(xr0[k0] * xj0);
                a[mt][1] = f2tf32(xr1[k0] * xj0);
                a[mt][2] = f2tf32(xr0[k0 + 4] * xj1);
                a[mt][3] = f2tf32(xr1[k0 + 4] * xj1);
            }
            // B fragments: rows k0, k0+4; col = warpn*32 + nt*8 + q
            const uint32_t* wk = Ws + (size_t)k0 * WS_PAD + warpn * 32 + q;
#pragma unroll
            for (int nt = 0; nt < 4; nt++) {
                uint32_t bf0 = wk[nt * 8];
                uint32_t bf1 = wk[4 * WS_PAD + nt * 8];
                mma_tf32(acc[0][nt], a[0], bf0, bf1);
                mma_tf32(acc[1][nt], a[1], bf0, bf1);
            }
        }

        // Epilogue: bias + relu + sum over i (rows), via shfl over q-lanes.
        // C layout: c0,c1 at (row=q, col=2*kq, 2*kq+1); c2,c3 at row=q+8.
        float* gout = g_buf + ((size_t)(b * NN + j)) * HH + h0 + warpn * 32;
#pragma unroll
        for (int nt = 0; nt < 4; nt++) {
            const float bx = b1v[nt].x, by = b1v[nt].y;
            float p0 = 0.f, p1 = 0.f;
#pragma unroll
            for (int mt = 0; mt < 2; mt++) {
                p0 += fmaxf(acc[mt][nt][0] + bx, 0.f) + fmaxf(acc[mt][nt][2] + bx, 0.f);
                p1 += fmaxf(acc[mt][nt][1] + by, 0.f) + fmaxf(acc[mt][nt][3] + by, 0.f);
            }
#pragma unroll
            for (int m = 4; m <= 16; m <<= 1) {
                p0 += __shfl_xor_sync(0xffffffffu, p0, m);
                p1 += __shfl_xor_sync(0xffffffffu, p1, m);
            }
            if (lane < 4)
                *reinterpret_cast<float2*>(gout + nt * 8 + 2 * lane) = make_float2(p0, p1);
        }
    }
}

// ======================= k2: out = g @ W2 + 32*b2 (fp32) ====================
// 128 blocks x 32 rows; thread tile 8x4; K chunks of 32.
__global__ __launch_bounds__(256) void k2(const float* __restrict__ W2,
                                          const float* __restrict__ b2,
                                          float* __restrict__ out)
{
    __shared__ __align__(16) float Gs[32][36];
    __shared__ __align__(16) float Ws2[32][260];
    const int row0 = blockIdx.x * 32;
    const int tid = threadIdx.x;
    const int gc = tid & 63, gr = tid >> 6;

    float acc[8][4];
#pragma unroll
    for (int r = 0; r < 8; r++)
#pragma unroll
        for (int c = 0; c < 4; c++) acc[r][c] = 0.f;

    for (int kc = 0; kc < HH; kc += 32) {
        __syncthreads();
        {   // Gs: 32 rows x 32 k
            int r = tid >> 3, c4 = tid & 7;
            *reinterpret_cast<float4*>(&Gs[r][c4 * 4]) =
                *reinterpret_cast<const float4*>(g_buf + (size_t)(row0 + r) * HH + kc + c4 * 4);
        }
        for (int t = tid; t < 2048; t += 256) {   // Ws2: 32 k x 256 d
            int e = t >> 6, c4 = t & 63;
            *reinterpret_cast<float4*>(&Ws2[e][c4 * 4]) =
                *reinterpret_cast<const float4*>(W2 + (size_t)(kc + e) * DD + c4 * 4);
        }
        __syncthreads();
#pragma unroll
        for (int e = 0; e < 32; e++) {
            float4 wv = *reinterpret_cast<const float4*>(&Ws2[e][gc * 4]);
#pragma unroll
            for (int r = 0; r < 8; r++) {
                float gvv = Gs[gr * 8 + r][e];
                acc[r][0] += gvv * wv.x; acc[r][1] += gvv * wv.y;
                acc[r][2] += gvv * wv.z; acc[r][3] += gvv * wv.w;
            }
        }
    }

    float4 bv = *reinterpret_cast<const float4*>(b2 + gc * 4);
#pragma unroll
    for (int r = 0; r < 8; r++) {
        float4 o;
        o.x = acc[r][0] + 32.f * bv.x;
        o.y = acc[r][1] + 32.f * bv.y;
        o.z = acc[r][2] + 32.f * bv.z;
        o.w = acc[r][3] + 32.f * bv.w;
        *reinterpret_cast<float4*>(out + (size_t)(row0 + gr * 8 + r) * DD + gc * 4) = o;
    }
}

// ======================= launcher ==========================================
extern "C" void kernel_launch(void* const* d_in, const int* in_sizes, int n_in,
                              void* d_out, int out_size)
{
    const float* X  = (const float*)d_in[0];   // [B,N,D]
    const float* W1 = (const float*)d_in[1];   // [D,H]
    const float* b1 = (const float*)d_in[2];   // [H]
    const float* W2 = (const float*)d_in[3];   // [H,D]
    const float* b2 = (const float*)d_in[4];   // [D]
    float* out = (float*)d_out;                // [B,N,D]

    cudaFuncSetAttribute(k1, cudaFuncAttributeMaxDynamicSharedMemorySize, K1_SMEM);

    k1<<<dim3(8, BB), 512, K1_SMEM>>>(X, W1, b1);
    k2<<<(BB * NN) / 32, 256>>>(W2, b2, out);
}